// round 17
// baseline (speedup 1.0000x reference)
#include <cuda_runtime.h>
#include <cuda_fp16.h>
#include <cstdint>
#include <math.h>

#define Nn 16
#define Hh 256
#define Ww 256
#define HW (Hh*Ww)

// ---------------- scratch (device globals; no allocation allowed) ----------------
__device__ __half g_h1x[(size_t)Nn*HW*64];
__device__ __half g_h1g[(size_t)Nn*HW*64];
__device__ __half g_h2x[(size_t)Nn*HW*64];
__device__ __half g_h2g[(size_t)Nn*HW*64];
__device__ float g_xy[(size_t)Nn*2*HW];
__device__ __align__(16) uint32_t g_wq8[3][9*8*2*32*4];    // fx2, fg2, c2
__device__ __align__(16) uint32_t g_wq11[2][9*11*2*32*4];  // fx3, fg3
__device__ __align__(16) uint32_t g_wq1[9*1*2*32*4];       // c3

__device__ __forceinline__ void mma_f16(float* c, const uint32_t* a, uint32_t b0, uint32_t b1) {
    asm volatile("mma.sync.aligned.m16n8k16.row.col.f32.f16.f16.f32 "
        "{%0,%1,%2,%3},{%4,%5,%6,%7},{%8,%9},{%0,%1,%2,%3};"
        : "+f"(c[0]), "+f"(c[1]), "+f"(c[2]), "+f"(c[3])
        : "r"(a[0]), "r"(a[1]), "r"(a[2]), "r"(a[3]), "r"(b0), "r"(b1));
}
__device__ __forceinline__ void ldm_x4(uint32_t* r, uint32_t saddr) {
    asm volatile("ldmatrix.sync.aligned.m8n8.x4.shared.b16 {%0,%1,%2,%3}, [%4];"
        : "=r"(r[0]), "=r"(r[1]), "=r"(r[2]), "=r"(r[3]) : "r"(saddr));
}
__device__ __forceinline__ uint32_t pkh2(float a, float b) {
    return (uint32_t)__half_as_ushort(__float2half_rn(a)) |
           ((uint32_t)__half_as_ushort(__float2half_rn(b)) << 16);
}
// cp.async with zero-fill when invalid (src-size = 0)
__device__ __forceinline__ void cpa16(uint32_t saddr, const void* gaddr, bool valid) {
    int sz = valid ? 16 : 0;
    asm volatile("cp.async.cg.shared.global [%0], [%1], 16, %2;"
        :: "r"(saddr), "l"(gaddr), "r"(sz));
}
__device__ __forceinline__ void cpa4(uint32_t saddr, const void* gaddr, bool valid) {
    int sz = valid ? 4 : 0;
    asm volatile("cp.async.ca.shared.global [%0], [%1], 4, %2;"
        :: "r"(saddr), "l"(gaddr), "r"(sz));
}
__device__ __forceinline__ void cpa_commit() {
    asm volatile("cp.async.commit_group;" ::: "memory");
}
template<int N>
__device__ __forceinline__ void cpa_wait() {
    asm volatile("cp.async.wait_group %0;" :: "n"(N) : "memory");
}

// ------------- weight prepack (all convs, one launch) ----------------
// per-conv layout: [tap][nt][k2][lane] x uint4
__device__ __forceinline__ void pk_one(const float* __restrict__ w, uint32_t* __restrict__ o,
                                       int NT, int CO, int idx) {
    int lane = idx & 31;
    int k2 = (idx >> 5) & 1;
    int nt = (idx >> 6) % NT;
    int tap = idx / (64*NT);
    int lg = lane >> 2, lt = lane & 3;
    int co = nt*8 + lg;
    uint32_t r[4];
    #pragma unroll
    for (int kk = 0; kk < 2; kk++) {
        int c0 = (k2*2 + kk)*16 + lt*2;
        float v0 = (co < CO) ? w[((size_t)co*64 + c0)*9 + tap] : 0.f;
        float v1 = (co < CO) ? w[((size_t)co*64 + c0+1)*9 + tap] : 0.f;
        float v2 = (co < CO) ? w[((size_t)co*64 + c0+8)*9 + tap] : 0.f;
        float v3 = (co < CO) ? w[((size_t)co*64 + c0+9)*9 + tap] : 0.f;
        r[kk*2+0] = pkh2(v0, v1);
        r[kk*2+1] = pkh2(v2, v3);
    }
    ((uint4*)o)[idx] = make_uint4(r[0], r[1], r[2], r[3]);
}

__global__ void prepack_all(
    const float* fx2, const float* fg2, const float* c2,
    const float* fx3, const float* fg3, const float* c3,
    uint32_t* o8, uint32_t* o11, uint32_t* o1)
{
    const int S8 = 9*8*2*32;     // 4608
    const int S11 = 9*11*2*32;   // 6336
    const int S1 = 9*1*2*32;     // 576
    const size_t W8 = (size_t)S8*4, W11 = (size_t)S11*4;
    int idx = blockIdx.x * 256 + threadIdx.x;
    if (idx < S8) { pk_one(fx2, o8, 8, 64, idx); return; }
    idx -= S8;
    if (idx < S8) { pk_one(fg2, o8 + W8, 8, 64, idx); return; }
    idx -= S8;
    if (idx < S8) { pk_one(c2, o8 + 2*W8, 8, 64, idx); return; }
    idx -= S8;
    if (idx < S11) { pk_one(fx3, o11, 11, 81, idx); return; }
    idx -= S11;
    if (idx < S11) { pk_one(fg3, o11 + W11, 11, 81, idx); return; }
    idx -= S11;
    if (idx < S1) { pk_one(c3, o1, 1, 1, idx); return; }
}

// ---------------- conv 3x3, small Cin -> 64 relu, writes fp16 NHWC. Optional 2 heads. ----
// PIX_BLOCKS per head = 4096 = 2^12.
template<int CIN, bool DUAL>
__global__ __launch_bounds__(256) void conv_in_small(
    const float* __restrict__ in0, const float* __restrict__ w0, const float* __restrict__ b0,
    __half* __restrict__ oh0,
    const float* __restrict__ in1, const float* __restrict__ w1, const float* __restrict__ b1,
    __half* __restrict__ oh1)
{
    __shared__ float s_w[64*CIN*9];
    __shared__ float s_b[64];
    int tid = threadIdx.x;
    int head = DUAL ? (int)(blockIdx.x >> 12) : 0;
    const float* in = head ? in1 : in0;
    const float* w  = head ? w1 : w0;
    const float* b  = head ? b1 : b0;
    __half* oh      = head ? oh1 : oh0;

    for (int i = tid; i < 64*CIN*9; i += 256) s_w[i] = w[i];
    if (tid < 64) s_b[tid] = b[tid];
    __syncthreads();

    int px = (DUAL ? (int)(blockIdx.x & 4095) : (int)blockIdx.x)*256 + tid;
    int n = px >> 16; int rem = px & 65535;
    int y = rem >> 8;  int x = rem & 255;

    float iv[CIN*9];
    #pragma unroll
    for (int c = 0; c < CIN; c++)
        #pragma unroll
        for (int kh = 0; kh < 3; kh++)
            #pragma unroll
            for (int kw = 0; kw < 3; kw++) {
                int yy = y + kh - 1, xx = x + kw - 1;
                float v = 0.f;
                if (yy >= 0 && yy < Hh && xx >= 0 && xx < Ww)
                    v = in[((size_t)n*CIN + c)*HW + yy*Ww + xx];
                iv[c*9 + kh*3 + kw] = v;
            }

    float a[64];
    #pragma unroll
    for (int co = 0; co < 64; co++) {
        float s = s_b[co];
        #pragma unroll
        for (int i = 0; i < CIN*9; i++) s += s_w[co*CIN*9 + i] * iv[i];
        a[co] = fmaxf(s, 0.f);
    }

    char* ph = (char*)oh + (size_t)px * 128;
    #pragma unroll
    for (int q = 0; q < 8; q++) {
        uint32_t hw[4];
        #pragma unroll
        for (int t = 0; t < 4; t++)
            hw[t] = pkh2(a[q*8 + t*2], a[q*8 + t*2 + 1]);
        *(uint4*)(ph + q*16) = make_uint4(hw[0], hw[1], hw[2], hw[3]);
    }
}

// ---------------- mma.sync conv 3x3, 64 -> CO, fp16, two-tile pipelined. --------------
// Per CTA: TWO y-adjacent tiles of 8 y-rows x 32 x (M=256 each), double-buffered A
// staged via cp.async up front; tile1's staging hides under tile0's mainloop.
// MODE: 0 = bias+relu -> fp16 NHWC; 1 = fused softmax+9x9 filter -> xy (window in smem);
//       2 = bias -> fp32 planar (channel 0 only)
// Blocks per head = 16n x 16yq2 x 8xq = 2048 = 2^11.
template<int NT, int CO, int MODE, bool DUAL>
__global__ __launch_bounds__(128, 2) void conv64m(
    const __half* __restrict__ ih0, const uint32_t* __restrict__ wq0,
    const float* __restrict__ bias0, __half* __restrict__ oh0, const float* __restrict__ fsrc0,
    const __half* __restrict__ ih1, const uint32_t* __restrict__ wq1,
    const float* __restrict__ bias1, __half* __restrict__ oh1, const float* __restrict__ fsrc1,
    float* __restrict__ xy)
{
    constexpr int CP = NT * 8;
    constexpr int AH = 10*34*144;         // 48960 bytes per tile buffer
    constexpr int FW = 16*40*4;           // 2560 bytes per window buffer
    extern __shared__ char sm[];
    char* sA0 = sm;
    char* sA1 = sm + AH;
    float* s_bias = (float*)(sm + 2*AH);
    float* sF0 = s_bias + CP;
    float* sF1 = sF0 + 16*40;

    int tid = threadIdx.x;
    int lane = tid & 31, wid = tid >> 5;
    int lg = lane >> 2, lt = lane & 3;

    int bid = blockIdx.x;
    int head = DUAL ? (bid >> 11) : 0;
    bid &= 2047;                          // 16n x 16yq2 x 8xq
    const __half* ih = head ? ih1 : ih0;
    const uint32_t* wq = head ? wq1 : wq0;
    const float* bias = head ? bias1 : bias0;
    __half* oh = head ? oh1 : oh0;
    const float* fsrc = head ? fsrc1 : fsrc0;

    int xq = bid & 7;
    int yq2 = (bid >> 3) & 15;
    int n  = bid >> 7;
    int x0 = xq * 32;
    size_t nbase = (size_t)n * 65536;

    if (tid < CP) s_bias[tid] = (tid < CO) ? bias[tid] : 0.f;

    uint32_t sA_s0 = (uint32_t)__cvta_generic_to_shared(sA0);
    uint32_t sF_s0 = (uint32_t)__cvta_generic_to_shared(sF0);

    // ---- issue cp.async for BOTH tiles (one commit group each) ----
    #pragma unroll
    for (int t = 0; t < 2; t++) {
        int y0 = yq2*16 + t*8;
        uint32_t sAb = sA_s0 + t*AH;
        for (int idx = tid; idx < 10*34*8; idx += 128) {
            int c = idx & 7, e = idx >> 3;
            int row = e / 34, px = e - row*34;
            int gy = y0 + row - 1, gx = x0 + px - 1;
            bool valid = ((unsigned)gy < 256u) && ((unsigned)gx < 256u);
            const char* src = (const char*)ih + (nbase + gy*256 + gx)*128 + c*16;
            cpa16(sAb + (uint32_t)((row*34 + px)*144 + c*16), src, valid);
        }
        if constexpr (MODE == 1) {
            const float* sp = fsrc + nbase;
            uint32_t sFb = sF_s0 + t*FW;
            for (int idx = tid; idx < 16*40; idx += 128) {
                int row = idx / 40, col = idx - row*40;
                int gy = y0 - 4 + row, gx = x0 - 4 + col;
                bool valid = ((unsigned)gy < 256u) && ((unsigned)gx < 256u);
                cpa4(sFb + (uint32_t)(idx*4), sp + gy*256 + gx, valid);
            }
        }
        cpa_commit();
    }

    uint32_t rbase = (uint32_t)((lane & 15) * 144 + ((lane >> 4) << 4));
    const uint4* wq4 = (const uint4*)wq;

    #pragma unroll
    for (int t = 0; t < 2; t++) {
        if (t == 0) cpa_wait<1>(); else cpa_wait<0>();
        __syncthreads();

        int y0 = yq2*16 + t*8;
        uint32_t sA_s = sA_s0 + t*AH;
        float* sF = t ? sF1 : sF0;

        float acc[4][NT][4];
        #pragma unroll
        for (int mt = 0; mt < 4; mt++)
            #pragma unroll
            for (int nt = 0; nt < NT; nt++)
                #pragma unroll
                for (int j = 0; j < 4; j++) acc[mt][nt][j] = 0.f;

        #pragma unroll 1
        for (int tap = 0; tap < 9; tap++) {
            int kh = tap / 3, kw = tap - kh*3;
            const uint4* wt = wq4 + (size_t)tap*NT*2*32 + lane;
            #pragma unroll
            for (int k2 = 0; k2 < 2; k2++) {
                uint32_t ah[2][4][4];   // [kk][mt][4], mt = r*2 + h
                #pragma unroll
                for (int kk = 0; kk < 2; kk++)
                    #pragma unroll
                    for (int r = 0; r < 2; r++)
                        #pragma unroll
                        for (int h = 0; h < 2; h++) {
                            uint32_t ad = sA_s +
                                (uint32_t)(((wid*2 + r + kh)*34 + h*16 + kw)*144) +
                                rbase + (k2*2 + kk)*32;
                            ldm_x4(ah[kk][r*2 + h], ad);
                        }
                #pragma unroll
                for (int nt = 0; nt < NT; nt++) {
                    uint4 bb = wt[(nt*2 + k2)*32];
                    #pragma unroll
                    for (int mt = 0; mt < 4; mt++) {
                        mma_f16(acc[mt][nt], ah[0][mt], bb.x, bb.y);
                        mma_f16(acc[mt][nt], ah[1][mt], bb.z, bb.w);
                    }
                }
            }
        }

        if constexpr (MODE == 0) {
            // bias + relu + fp16 global
            #pragma unroll
            for (int mt = 0; mt < 4; mt++) {
                int r = mt >> 1, h = mt & 1;
                int Y = y0 + wid*2 + r;
                size_t pix0 = nbase + (size_t)Y*256 + x0 + h*16 + lg;
                #pragma unroll
                for (int nt = 0; nt < NT; nt++) {
                    int co = nt*8 + lt*2;
                    float b0 = s_bias[co], b1v = s_bias[co+1];
                    *(uint32_t*)((char*)oh + pix0*128 + co*2) =
                        pkh2(fmaxf(acc[mt][nt][0] + b0, 0.f), fmaxf(acc[mt][nt][1] + b1v, 0.f));
                    *(uint32_t*)((char*)oh + (pix0+8)*128 + co*2) =
                        pkh2(fmaxf(acc[mt][nt][2] + b0, 0.f), fmaxf(acc[mt][nt][3] + b1v, 0.f));
                }
            }
        } else if constexpr (MODE == 1) {
            // fused softmax over 81 logits + 9x9 pixel-adaptive filtering (window in smem)
            #pragma unroll
            for (int mt = 0; mt < 4; mt++) {
                int r = mt >> 1, h = mt & 1;
                int yw = wid*2 + r;
                #pragma unroll
                for (int rr = 0; rr < 2; rr++) {
                    int xw = h*16 + lg + rr*8;
                    float v[NT][2];
                    float mx = -1e30f;
                    #pragma unroll
                    for (int nt = 0; nt < NT; nt++) {
                        #pragma unroll
                        for (int j = 0; j < 2; j++) {
                            int co = nt*8 + lt*2 + j;
                            v[nt][j] = acc[mt][nt][rr*2 + j] + s_bias[co];
                            if (co < 81) mx = fmaxf(mx, v[nt][j]);
                        }
                    }
                    mx = fmaxf(mx, __shfl_xor_sync(0xffffffffu, mx, 1));
                    mx = fmaxf(mx, __shfl_xor_sync(0xffffffffu, mx, 2));
                    float se = 0.f, fo = 0.f;
                    #pragma unroll
                    for (int nt = 0; nt < NT; nt++) {
                        #pragma unroll
                        for (int j = 0; j < 2; j++) {
                            int co = nt*8 + lt*2 + j;
                            if (co < 81) {
                                float e = __expf(v[nt][j] - mx);
                                se += e;
                                int kh = co / 9, kw = co - kh*9;
                                fo += e * sF[(yw + kh)*40 + xw + kw];
                            }
                        }
                    }
                    se += __shfl_xor_sync(0xffffffffu, se, 1);
                    se += __shfl_xor_sync(0xffffffffu, se, 2);
                    fo += __shfl_xor_sync(0xffffffffu, fo, 1);
                    fo += __shfl_xor_sync(0xffffffffu, fo, 2);
                    if (lt == 0)
                        xy[((size_t)n*2 + head)*HW + (y0 + yw)*256 + x0 + xw] = fo / se;
                }
            }
        } else {
            // MODE 2: fp32 planar out, channel 0 only
            float b0 = s_bias[0];
            if (lt == 0) {
                #pragma unroll
                for (int mt = 0; mt < 4; mt++) {
                    int r = mt >> 1, h = mt & 1;
                    int Y = y0 + wid*2 + r;
                    #pragma unroll
                    for (int rr = 0; rr < 2; rr++) {
                        int X = x0 + h*16 + lg + rr*8;
                        xy[nbase + (size_t)Y*256 + X] = acc[mt][0][rr*2] + b0;
                    }
                }
            }
        }
    }
}

// ---------------- launch ----------------
extern "C" void kernel_launch(void* const* d_in, const int* in_sizes, int n_in,
                              void* d_out, int out_size)
{
    const float* x     = (const float*)d_in[0];
    const float* g     = (const float*)d_in[1];
    const float* fx_w1 = (const float*)d_in[2];
    const float* fx_b1 = (const float*)d_in[3];
    const float* fx_w2 = (const float*)d_in[4];
    const float* fx_b2 = (const float*)d_in[5];
    const float* fx_w3 = (const float*)d_in[6];
    const float* fx_b3 = (const float*)d_in[7];
    const float* fg_w1 = (const float*)d_in[8];
    const float* fg_b1 = (const float*)d_in[9];
    const float* fg_w2 = (const float*)d_in[10];
    const float* fg_b2 = (const float*)d_in[11];
    const float* fg_w3 = (const float*)d_in[12];
    const float* fg_b3 = (const float*)d_in[13];
    const float* c1_w  = (const float*)d_in[14];
    const float* c1_b  = (const float*)d_in[15];
    const float* c2_w  = (const float*)d_in[16];
    const float* c2_b  = (const float*)d_in[17];
    const float* c3_w  = (const float*)d_in[18];
    const float* c3_b  = (const float*)d_in[19];
    float* out = (float*)d_out;

    __half *h1x, *h1g, *h2x, *h2g;
    float *xy; uint32_t *wq8, *wq11, *wq1;
    cudaGetSymbolAddress((void**)&h1x, g_h1x);
    cudaGetSymbolAddress((void**)&h1g, g_h1g);
    cudaGetSymbolAddress((void**)&h2x, g_h2x);
    cudaGetSymbolAddress((void**)&h2g, g_h2g);
    cudaGetSymbolAddress((void**)&xy, g_xy);
    cudaGetSymbolAddress((void**)&wq8, g_wq8);
    cudaGetSymbolAddress((void**)&wq11, g_wq11);
    cudaGetSymbolAddress((void**)&wq1, g_wq1);

    const size_t W8 = 9*8*2*32*4;
    const size_t W11 = 9*11*2*32*4;
    uint32_t* wq_fx2 = wq8;
    uint32_t* wq_fg2 = wq8 + W8;
    uint32_t* wq_c2  = wq8 + 2*W8;
    uint32_t* wq_fx3 = wq11;
    uint32_t* wq_fg3 = wq11 + W11;

    const int PIX_BLOCKS = Nn*HW/256;      // 4096
    const int C64_BLOCKS = Nn*16*8;        // 2048 (two tiles per CTA)

    const int AH = 10*34*144;              // 48960
    const int SM64 = 2*AH + 64*4;
    const int SM88 = 2*AH + 88*4 + 2*16*40*4;
    const int SM8  = 2*AH + 8*4;

    cudaFuncSetAttribute((const void*)conv64m<8, 64, 0, true>,
                         cudaFuncAttributeMaxDynamicSharedMemorySize, SM64);
    cudaFuncSetAttribute((const void*)conv64m<8, 64, 0, false>,
                         cudaFuncAttributeMaxDynamicSharedMemorySize, SM64);
    cudaFuncSetAttribute((const void*)conv64m<11, 81, 1, true>,
                         cudaFuncAttributeMaxDynamicSharedMemorySize, SM88);
    cudaFuncSetAttribute((const void*)conv64m<1, 1, 2, false>,
                         cudaFuncAttributeMaxDynamicSharedMemorySize, SM8);

    // ---- single fused weight prepack ----
    const int PK_TOTAL = 3*(9*8*2*32) + 2*(9*11*2*32) + 9*1*2*32;  // 27072
    prepack_all<<<(PK_TOTAL + 255)/256, 256>>>(
        fx_w2, fg_w2, c2_w, fx_w3, fg_w3, c3_w, wq8, wq11, wq1);

    // ---- batched x+g heads ----
    conv_in_small<1, true><<<2*PIX_BLOCKS, 256>>>(
        x, fx_w1, fx_b1, h1x, g, fg_w1, fg_b1, h1g);
    conv64m<8, 64, 0, true><<<2*C64_BLOCKS, 128, SM64>>>(
        h1x, wq_fx2, fx_b2, h2x, nullptr,
        h1g, wq_fg2, fg_b2, h2g, nullptr, nullptr);
    conv64m<11, 81, 1, true><<<2*C64_BLOCKS, 128, SM88>>>(
        h2x, wq_fx3, fx_b3, nullptr, x,
        h2g, wq_fg3, fg_b3, nullptr, g, xy);

    // ---- fusion head ----
    conv_in_small<2, false><<<PIX_BLOCKS, 256>>>(
        xy, c1_w, c1_b, h1x, nullptr, nullptr, nullptr, nullptr);
    conv64m<8, 64, 0, false><<<C64_BLOCKS, 128, SM64>>>(
        h1x, wq_c2, c2_b, h2x, nullptr,
        nullptr, nullptr, nullptr, nullptr, nullptr, nullptr);
    conv64m<1, 1, 2, false><<<C64_BLOCKS, 128, SM8>>>(
        h2x, wq1, c3_b, nullptr, nullptr,
        nullptr, nullptr, nullptr, nullptr, nullptr, out);
}